// round 1
// baseline (speedup 1.0000x reference)
#include <cuda_runtime.h>
#include <math.h>

#define NTOK 16384
#define KDIM 768
#define KHID 3072
#define NEXP 5

#define BM 128
#define BN 128
#define BK 16

// ---- device scratch (static globals: allocation-free per harness rules) ----
__device__ int   g_count[NEXP];
__device__ int   g_tok[NEXP * NTOK];
__device__ float g_gate[NEXP * NTOK];
__device__ float g_H[(size_t)NTOK * KHID];   // 192 MiB expert hidden scratch (reused per expert)

// ---------------------------------------------------------------------------
__global__ void zero_counts_kernel() {
    if (threadIdx.x < NEXP) g_count[threadIdx.x] = 0;
}

// One warp per token: logits = x @ w_gate, top-2, softmax over the 2,
// append (token, gate) to each selected expert's list.
__global__ void gating_kernel(const float* __restrict__ x, const float* __restrict__ wg) {
    int t    = (blockIdx.x * blockDim.x + threadIdx.x) >> 5;
    int lane = threadIdx.x & 31;
    if (t >= NTOK) return;
    const float* xr = x + (size_t)t * KDIM;

    float p0 = 0.f, p1 = 0.f, p2 = 0.f, p3 = 0.f, p4 = 0.f;
    for (int k = lane; k < KDIM; k += 32) {
        float xv = xr[k];
        const float* w = wg + (size_t)k * NEXP;
        p0 += xv * w[0]; p1 += xv * w[1]; p2 += xv * w[2];
        p3 += xv * w[3]; p4 += xv * w[4];
    }
#pragma unroll
    for (int o = 16; o > 0; o >>= 1) {
        p0 += __shfl_down_sync(0xffffffffu, p0, o);
        p1 += __shfl_down_sync(0xffffffffu, p1, o);
        p2 += __shfl_down_sync(0xffffffffu, p2, o);
        p3 += __shfl_down_sync(0xffffffffu, p3, o);
        p4 += __shfl_down_sync(0xffffffffu, p4, o);
    }
    if (lane == 0) {
        float v[NEXP] = {p0, p1, p2, p3, p4};
        int i0 = 0; float v0 = v[0];
#pragma unroll
        for (int e = 1; e < NEXP; e++) if (v[e] > v0) { v0 = v[e]; i0 = e; }
        int i1 = -1; float v1 = -3.4e38f;
#pragma unroll
        for (int e = 0; e < NEXP; e++) if (e != i0 && v[e] > v1) { v1 = v[e]; i1 = e; }
        // softmax over [v0, v1], v0 >= v1
        float e1 = expf(v1 - v0);
        float s  = 1.0f + e1;
        float g0 = 1.0f / s;
        float g1 = e1 / s;
        int q0 = atomicAdd(&g_count[i0], 1);
        g_tok[i0 * NTOK + q0]  = t;
        g_gate[i0 * NTOK + q0] = g0;
        int q1 = atomicAdd(&g_count[i1], 1);
        g_tok[i1 * NTOK + q1]  = t;
        g_gate[i1 * NTOK + q1] = g1;
    }
}

__device__ __forceinline__ float gelu_erf(float v) {
    return 0.5f * v * (1.0f + erff(v * 0.70710678118654752f));
}

// ---------------------------------------------------------------------------
// fc1: H[i, :] = gelu( x[tok[i], :] @ W1[e] + b1[e] ) for i < count[e]
// Tiled fp32 SGEMM, gathered A rows. Grid: (KHID/BN, NTOK/BM)
__global__ __launch_bounds__(256, 2)
void fc1_kernel(const float* __restrict__ x,
                const float* __restrict__ W1, const float* __restrict__ b1, int e)
{
    __shared__ float As[BK][BM];
    __shared__ float Bs[BK][BN];

    int cnt  = g_count[e];
    int row0 = blockIdx.y * BM;
    if (row0 >= cnt) return;
    int col0 = blockIdx.x * BN;

    const float* W    = W1 + (size_t)e * KDIM * KHID;
    const int*   tokp = g_tok + e * NTOK + row0;

    int tid = threadIdx.x;
    int tx = tid & 15, ty = tid >> 4;

    // A-tile load mapping: 512 float4 / 256 threads = 2 each
    int ar0 = tid >> 2;           // rows 0..63
    int ar1 = ar0 + 64;           // rows 64..127
    int akq = (tid & 3) * 4;      // k offset 0,4,8,12
    int tokA0 = (row0 + ar0 < cnt) ? tokp[ar0] : -1;
    int tokA1 = (row0 + ar1 < cnt) ? tokp[ar1] : -1;

    // B-tile load mapping
    int bk0 = tid >> 5;           // k rows 0..7
    int bk1 = bk0 + 8;            // k rows 8..15
    int bj  = (tid & 31) * 4;     // col offset

    float acc[8][8];
#pragma unroll
    for (int i = 0; i < 8; i++)
#pragma unroll
        for (int j = 0; j < 8; j++) acc[i][j] = 0.f;

    for (int k0 = 0; k0 < KDIM; k0 += BK) {
        float4 a0 = make_float4(0.f, 0.f, 0.f, 0.f), a1 = a0;
        if (tokA0 >= 0) a0 = *(const float4*)(x + (size_t)tokA0 * KDIM + k0 + akq);
        if (tokA1 >= 0) a1 = *(const float4*)(x + (size_t)tokA1 * KDIM + k0 + akq);
        As[akq + 0][ar0] = a0.x; As[akq + 1][ar0] = a0.y;
        As[akq + 2][ar0] = a0.z; As[akq + 3][ar0] = a0.w;
        As[akq + 0][ar1] = a1.x; As[akq + 1][ar1] = a1.y;
        As[akq + 2][ar1] = a1.z; As[akq + 3][ar1] = a1.w;

        float4 bv0 = *(const float4*)(W + (size_t)(k0 + bk0) * KHID + col0 + bj);
        float4 bv1 = *(const float4*)(W + (size_t)(k0 + bk1) * KHID + col0 + bj);
        *(float4*)&Bs[bk0][bj] = bv0;
        *(float4*)&Bs[bk1][bj] = bv1;
        __syncthreads();

#pragma unroll
        for (int k = 0; k < BK; k++) {
            float4 aA = *(const float4*)&As[k][ty * 8];
            float4 aB = *(const float4*)&As[k][ty * 8 + 4];
            float4 bA = *(const float4*)&Bs[k][tx * 8];
            float4 bB = *(const float4*)&Bs[k][tx * 8 + 4];
            float a[8] = {aA.x, aA.y, aA.z, aA.w, aB.x, aB.y, aB.z, aB.w};
            float b[8] = {bA.x, bA.y, bA.z, bA.w, bB.x, bB.y, bB.z, bB.w};
#pragma unroll
            for (int i = 0; i < 8; i++)
#pragma unroll
                for (int j = 0; j < 8; j++) acc[i][j] += a[i] * b[j];
        }
        __syncthreads();
    }

    float bias[8];
    const float* bb = b1 + (size_t)e * KHID + col0 + tx * 8;
#pragma unroll
    for (int j = 0; j < 8; j++) bias[j] = bb[j];

#pragma unroll
    for (int i = 0; i < 8; i++) {
        int gr = row0 + ty * 8 + i;
        if (gr < cnt) {
            float* Hp = g_H + (size_t)gr * KHID + col0 + tx * 8;
#pragma unroll
            for (int j = 0; j < 8; j++) Hp[j] = gelu_erf(acc[i][j] + bias[j]);
        }
    }
}

// ---------------------------------------------------------------------------
// fc2: out[tok[i], :] += gate[i] * exp( H[i, :] @ W2[e] + b2[e] )
// Grid: (KDIM/BN, NTOK/BM). Experts serialize on the stream -> no races.
__global__ __launch_bounds__(256, 2)
void fc2_kernel(const float* __restrict__ W2, const float* __restrict__ b2,
                float* __restrict__ out, int e)
{
    __shared__ float As[BK][BM];
    __shared__ float Bs[BK][BN];

    int cnt  = g_count[e];
    int row0 = blockIdx.y * BM;
    if (row0 >= cnt) return;
    int col0 = blockIdx.x * BN;

    const float* W = W2 + (size_t)e * KHID * KDIM;

    int tid = threadIdx.x;
    int tx = tid & 15, ty = tid >> 4;

    int ar0 = tid >> 2;
    int ar1 = ar0 + 64;
    int akq = (tid & 3) * 4;

    int bk0 = tid >> 5;
    int bk1 = bk0 + 8;
    int bj  = (tid & 31) * 4;

    float acc[8][8];
#pragma unroll
    for (int i = 0; i < 8; i++)
#pragma unroll
        for (int j = 0; j < 8; j++) acc[i][j] = 0.f;

    for (int k0 = 0; k0 < KHID; k0 += BK) {
        // A rows are list positions (contiguous in g_H); garbage rows beyond cnt
        // are finite and discarded in the epilogue.
        float4 a0 = *(const float4*)(g_H + (size_t)(row0 + ar0) * KHID + k0 + akq);
        float4 a1 = *(const float4*)(g_H + (size_t)(row0 + ar1) * KHID + k0 + akq);
        As[akq + 0][ar0] = a0.x; As[akq + 1][ar0] = a0.y;
        As[akq + 2][ar0] = a0.z; As[akq + 3][ar0] = a0.w;
        As[akq + 0][ar1] = a1.x; As[akq + 1][ar1] = a1.y;
        As[akq + 2][ar1] = a1.z; As[akq + 3][ar1] = a1.w;

        float4 bv0 = *(const float4*)(W + (size_t)(k0 + bk0) * KDIM + col0 + bj);
        float4 bv1 = *(const float4*)(W + (size_t)(k0 + bk1) * KDIM + col0 + bj);
        *(float4*)&Bs[bk0][bj] = bv0;
        *(float4*)&Bs[bk1][bj] = bv1;
        __syncthreads();

#pragma unroll
        for (int k = 0; k < BK; k++) {
            float4 aA = *(const float4*)&As[k][ty * 8];
            float4 aB = *(const float4*)&As[k][ty * 8 + 4];
            float4 bA = *(const float4*)&Bs[k][tx * 8];
            float4 bB = *(const float4*)&Bs[k][tx * 8 + 4];
            float a[8] = {aA.x, aA.y, aA.z, aA.w, aB.x, aB.y, aB.z, aB.w};
            float b[8] = {bA.x, bA.y, bA.z, bA.w, bB.x, bB.y, bB.z, bB.w};
#pragma unroll
            for (int i = 0; i < 8; i++)
#pragma unroll
                for (int j = 0; j < 8; j++) acc[i][j] += a[i] * b[j];
        }
        __syncthreads();
    }

    float bias[8];
    const float* bb = b2 + (size_t)e * KDIM + col0 + tx * 8;
#pragma unroll
    for (int j = 0; j < 8; j++) bias[j] = bb[j];

#pragma unroll
    for (int i = 0; i < 8; i++) {
        int gr = row0 + ty * 8 + i;
        if (gr < cnt) {
            int   tok = g_tok[e * NTOK + gr];
            float g   = g_gate[e * NTOK + gr];
            float* op = out + (size_t)tok * KDIM + col0 + tx * 8;
#pragma unroll
            for (int j = 0; j < 8; j++) {
                float y = acc[i][j] + bias[j];
                op[j] += g * expf(y);
            }
        }
    }
}

// ---------------------------------------------------------------------------
__global__ void finalize_kernel(float* __restrict__ out, int n) {
    int i = blockIdx.x * blockDim.x + threadIdx.x;
    if (i < n) {
        float v = out[i];
        out[i] = logf(v == 0.0f ? 2.2204460492503131e-16f : v);
    }
}

// ---------------------------------------------------------------------------
extern "C" void kernel_launch(void* const* d_in, const int* in_sizes, int n_in,
                              void* d_out, int out_size) {
    const float* x  = (const float*)d_in[0];
    const float* wg = (const float*)d_in[1];
    const float* W1 = (const float*)d_in[2];
    const float* b1 = (const float*)d_in[3];
    const float* W2 = (const float*)d_in[4];
    const float* b2 = (const float*)d_in[5];
    float* out = (float*)d_out;

    cudaMemsetAsync(out, 0, (size_t)NTOK * KDIM * sizeof(float), 0);
    zero_counts_kernel<<<1, 32>>>();
    gating_kernel<<<(NTOK * 32 + 255) / 256, 256>>>(x, wg);

    for (int e = 0; e < NEXP; e++) {
        dim3 g1(KHID / BN, NTOK / BM);   // (24, 128)
        fc1_kernel<<<g1, 256>>>(x, W1, b1, e);
        dim3 g2(KDIM / BN, NTOK / BM);   // (6, 128)
        fc2_kernel<<<g2, 256>>>(W2, b2, out, e);
    }

    finalize_kernel<<<(NTOK * KDIM + 255) / 256, 256>>>(out, NTOK * KDIM);
}

// round 6
// speedup vs baseline: 1.2035x; 1.2035x over previous
#include <cuda_runtime.h>
#include <cuda_bf16.h>
#include <math.h>
#include <stdint.h>

#define NTOK 16384
#define KDIM 768
#define KHID 3072
#define NEXP 5

// ---------------- device scratch (static, allocation-free) ----------------
__device__ int   g_count[NEXP];
__device__ int   g_tok[NEXP * NTOK];
__device__ float g_gate[NEXP * NTOK];
__device__ float g_H[(size_t)NTOK * KHID];   // fp32 hidden scratch (R1 format)

// ---------------- helpers ----------------
__device__ __forceinline__ void mma16816(float (&c)[4], const uint32_t (&a)[4],
                                         uint32_t b0, uint32_t b1) {
    asm volatile("mma.sync.aligned.m16n8k16.row.col.f32.bf16.bf16.f32 "
                 "{%0,%1,%2,%3}, {%4,%5,%6,%7}, {%8,%9}, {%0,%1,%2,%3};"
                 : "+f"(c[0]), "+f"(c[1]), "+f"(c[2]), "+f"(c[3])
                 : "r"(a[0]), "r"(a[1]), "r"(a[2]), "r"(a[3]), "r"(b0), "r"(b1));
}
// split (fx, fy) into packed bf16x2 hi and bf16x2 lo (residual)
__device__ __forceinline__ void split2(float fx, float fy, uint32_t& hi, uint32_t& lo) {
    __nv_bfloat162 H, L;
    H.x = __float2bfloat16(fx);
    H.y = __float2bfloat16(fy);
    L.x = __float2bfloat16(fx - __bfloat162float(H.x));
    L.y = __float2bfloat16(fy - __bfloat162float(H.y));
    hi = *reinterpret_cast<uint32_t*>(&H);
    lo = *reinterpret_cast<uint32_t*>(&L);
}
__device__ __forceinline__ float gelu_erf(float v) {
    return 0.5f * v * (1.0f + erff(v * 0.70710678118654752f));
}

// ---------------------------------------------------------------------------
__global__ void zero_counts_kernel() {
    if (threadIdx.x < NEXP) g_count[threadIdx.x] = 0;
}

// R1-proven gating
__global__ void gating_kernel(const float* __restrict__ x, const float* __restrict__ wg) {
    int t = (blockIdx.x * blockDim.x + threadIdx.x) >> 5;
    int lane = threadIdx.x & 31;
    if (t >= NTOK) return;
    const float* xr = x + (size_t)t * KDIM;
    float p0 = 0.f, p1 = 0.f, p2 = 0.f, p3 = 0.f, p4 = 0.f;
    for (int k = lane; k < KDIM; k += 32) {
        float xv = xr[k];
        const float* w = wg + (size_t)k * NEXP;
        p0 += xv * w[0]; p1 += xv * w[1]; p2 += xv * w[2]; p3 += xv * w[3]; p4 += xv * w[4];
    }
#pragma unroll
    for (int o = 16; o > 0; o >>= 1) {
        p0 += __shfl_down_sync(0xffffffffu, p0, o);
        p1 += __shfl_down_sync(0xffffffffu, p1, o);
        p2 += __shfl_down_sync(0xffffffffu, p2, o);
        p3 += __shfl_down_sync(0xffffffffu, p3, o);
        p4 += __shfl_down_sync(0xffffffffu, p4, o);
    }
    if (lane == 0) {
        float v[NEXP] = {p0, p1, p2, p3, p4};
        int i0 = 0; float v0 = v[0];
#pragma unroll
        for (int e = 1; e < NEXP; e++) if (v[e] > v0) { v0 = v[e]; i0 = e; }
        int i1 = -1; float v1 = -3.4e38f;
#pragma unroll
        for (int e = 0; e < NEXP; e++) if (e != i0 && v[e] > v1) { v1 = v[e]; i1 = e; }
        float e1 = expf(v1 - v0);
        float s = 1.0f + e1;
        int q0 = atomicAdd(&g_count[i0], 1);
        g_tok[i0 * NTOK + q0] = t;  g_gate[i0 * NTOK + q0] = 1.0f / s;
        int q1 = atomicAdd(&g_count[i1], 1);
        g_tok[i1 * NTOK + q1] = t;  g_gate[i1 * NTOK + q1] = e1 / s;
    }
}

// ---------------------------------------------------------------------------
// fc1 via mma.sync with IN-REGISTER bf16 hi/lo split (3-term: ahbh+albh+ahbl).
// A: gathered fp32 rows of x [128 x 16 per chunk]; B: fp32 W1 tile [16 x 128].
// No preprocessing kernels, no bf16 globals — fp32 LDG->STS exactly like R1.
#define F1_CK 16
#define A_STR 20     // floats per SMEM A row (16 + pad, 80B = 16B-aligned)
#define B_STR 136    // floats per SMEM B row (128 + pad, 544B = 16B-aligned)

__global__ __launch_bounds__(256, 1)
void fc1_mma_kernel(const float* __restrict__ x, const float* __restrict__ W1,
                    const float* __restrict__ b1, int e) {
    int cnt = g_count[e];
    int row0 = blockIdx.y * 128;
    if (row0 >= cnt) return;
    int col0 = blockIdx.x * 128;

    __shared__ float sA[2][128 * A_STR];
    __shared__ float sB[2][F1_CK * B_STR];
    __shared__ float s_bias[128];

    int tid = threadIdx.x, wid = tid >> 5, lane = tid & 31;
    int wm = (wid & 3) * 32, wn = (wid >> 2) * 64;
    int g = lane >> 2, t4 = lane & 3;

    if (tid < 128) s_bias[tid] = b1[(size_t)e * KHID + col0 + tid];

    // A loader: thread -> (row lr, 8-float half lh). Gather token id once.
    int lr = tid >> 1, lh = tid & 1;
    int arow = row0 + lr;
    int tokA = g_tok[e * NTOK + (arow < cnt ? arow : row0)];
    const float* aSrc = x + (size_t)tokA * KDIM + lh * 8;
    // B loader: thread -> (k-row kr, 8-float segment seg)
    int kr = tid >> 4, seg = tid & 15;
    const float* bSrc = W1 + (size_t)e * KDIM * KHID + (size_t)kr * KHID + col0 + seg * 8;

    float4 ra0, ra1, rb0, rb1;
    auto ldg = [&](int c) {
        const float* ap = aSrc + c * F1_CK;
        ra0 = *(const float4*)ap;       ra1 = *(const float4*)(ap + 4);
        const float* bp = bSrc + (size_t)c * F1_CK * KHID;
        rb0 = *(const float4*)bp;       rb1 = *(const float4*)(bp + 4);
    };
    auto sts = [&](int s) {
        float* pa = &sA[s][lr * A_STR + lh * 8];
        *(float4*)pa = ra0;  *(float4*)(pa + 4) = ra1;
        float* pb = &sB[s][kr * B_STR + seg * 8];
        *(float4*)pb = rb0;  *(float4*)(pb + 4) = rb1;
    };

    float acc[2][8][4];
#pragma unroll
    for (int i = 0; i < 2; i++)
#pragma unroll
        for (int j = 0; j < 8; j++)
#pragma unroll
            for (int k = 0; k < 4; k++) acc[i][j][k] = 0.f;

    const int NC = KDIM / F1_CK;   // 48
    ldg(0);
    sts(0);

    for (int c = 0; c < NC; c++) {
        __syncthreads();
        if (c + 1 < NC) ldg(c + 1);

        const float* A = sA[c & 1];
        const float* B = sB[c & 1];

        // --- A fragments: a0=(row g,k 2t4..+1), a1=(g+8,k), a2=(g,k+8), a3=(g+8,k+8)
        uint32_t ah[2][4], al[2][4];
#pragma unroll
        for (int mt = 0; mt < 2; mt++) {
            int r0 = wm + mt * 16 + g;
            float2 f0 = *(const float2*)&A[r0 * A_STR + 2 * t4];
            float2 f1 = *(const float2*)&A[(r0 + 8) * A_STR + 2 * t4];
            float2 f2 = *(const float2*)&A[r0 * A_STR + 2 * t4 + 8];
            float2 f3 = *(const float2*)&A[(r0 + 8) * A_STR + 2 * t4 + 8];
            split2(f0.x, f0.y, ah[mt][0], al[mt][0]);
            split2(f1.x, f1.y, ah[mt][1], al[mt][1]);
            split2(f2.x, f2.y, ah[mt][2], al[mt][2]);
            split2(f3.x, f3.y, ah[mt][3], al[mt][3]);
        }
#pragma unroll
        for (int np = 0; np < 4; np++) {
            int n0 = wn + np * 16 + g;
            // B fragments (col-major KxN): b0={B[2t4][n],B[2t4+1][n]}, b1={B[2t4+8][n],B[2t4+9][n]}
            uint32_t bh[4], bl[4];
            split2(B[(2 * t4) * B_STR + n0],         B[(2 * t4 + 1) * B_STR + n0],     bh[0], bl[0]);
            split2(B[(2 * t4 + 8) * B_STR + n0],     B[(2 * t4 + 9) * B_STR + n0],     bh[1], bl[1]);
            split2(B[(2 * t4) * B_STR + n0 + 8],     B[(2 * t4 + 1) * B_STR + n0 + 8], bh[2], bl[2]);
            split2(B[(2 * t4 + 8) * B_STR + n0 + 8], B[(2 * t4 + 9) * B_STR + n0 + 8], bh[3], bl[3]);
#pragma unroll
            for (int mt = 0; mt < 2; mt++) {
                mma16816(acc[mt][np * 2 + 0], ah[mt], bh[0], bh[1]);
                mma16816(acc[mt][np * 2 + 0], al[mt], bh[0], bh[1]);
                mma16816(acc[mt][np * 2 + 0], ah[mt], bl[0], bl[1]);
                mma16816(acc[mt][np * 2 + 1], ah[mt], bh[2], bh[3]);
                mma16816(acc[mt][np * 2 + 1], al[mt], bh[2], bh[3]);
                mma16816(acc[mt][np * 2 + 1], ah[mt], bl[2], bl[3]);
            }
        }
        if (c + 1 < NC) sts((c + 1) & 1);
    }

    // --- epilogue: gelu(acc + bias) -> g_H (fp32, list-position rows, R1 layout)
#pragma unroll
    for (int mt = 0; mt < 2; mt++) {
        int gr0 = row0 + wm + mt * 16 + g;
        int gr1 = gr0 + 8;
#pragma unroll
        for (int nj = 0; nj < 8; nj++) {
            int cloc = wn + nj * 8 + 2 * t4;
            float b0v = s_bias[cloc], b1v = s_bias[cloc + 1];
            size_t o0 = (size_t)gr0 * KHID + col0 + cloc;
            size_t o1 = (size_t)gr1 * KHID + col0 + cloc;
            if (gr0 < cnt) {
                g_H[o0]     = gelu_erf(acc[mt][nj][0] + b0v);
                g_H[o0 + 1] = gelu_erf(acc[mt][nj][1] + b1v);
            }
            if (gr1 < cnt) {
                g_H[o1]     = gelu_erf(acc[mt][nj][2] + b0v);
                g_H[o1 + 1] = gelu_erf(acc[mt][nj][3] + b1v);
            }
        }
    }
}

// ---------------------------------------------------------------------------
// fc2: VERBATIM R1 FFMA kernel (proven). out[tok] += gate * exp(H @ W2 + b2)
#define BM 128
#define BN 128
#define BK 16
__global__ __launch_bounds__(256, 2)
void fc2_kernel(const float* __restrict__ W2, const float* __restrict__ b2,
                float* __restrict__ out, int e)
{
    __shared__ float As[BK][BM];
    __shared__ float Bs[BK][BN];

    int cnt  = g_count[e];
    int row0 = blockIdx.y * BM;
    if (row0 >= cnt) return;
    int col0 = blockIdx.x * BN;

    const float* W = W2 + (size_t)e * KHID * KDIM;

    int tid = threadIdx.x;
    int tx = tid & 15, ty = tid >> 4;

    int ar0 = tid >> 2;
    int ar1 = ar0 + 64;
    int akq = (tid & 3) * 4;

    int bk0 = tid >> 5;
    int bk1 = bk0 + 8;
    int bj  = (tid & 31) * 4;

    float acc[8][8];
#pragma unroll
    for (int i = 0; i < 8; i++)
#pragma unroll
        for (int j = 0; j < 8; j++) acc[i][j] = 0.f;

    for (int k0 = 0; k0 < KHID; k0 += BK) {
        float4 a0 = *(const float4*)(g_H + (size_t)(row0 + ar0) * KHID + k0 + akq);
        float4 a1 = *(const float4*)(g_H + (size_t)(row0 + ar1) * KHID + k0 + akq);
        As[akq + 0][ar0] = a0.x; As[akq + 1][ar0] = a0.y;
        As[akq + 2][ar0] = a0.z; As[akq + 3][ar0] = a0.w;
        As[akq + 0][ar1] = a1.x; As[akq + 1][ar1] = a1.y;
        As[akq + 2][ar1] = a1.z; As[akq + 3][ar1] = a1.w;

        float4 bv0 = *(const float4*)(W + (size_t)(k0 + bk0) * KDIM + col0 + bj);
        float4 bv1 = *(const float4*)(W + (size_t)(k0 + bk1) * KDIM + col0 + bj);
        *(float4*)&Bs[bk0][bj] = bv0;
        *(float4*)&Bs[bk1][bj] = bv1;
        __syncthreads();

#pragma unroll
        for (int k = 0; k < BK; k++) {
            float4 aA = *(const float4*)&As[k][ty * 8];
            float4 aB = *(const float4*)&As[k][ty * 8 + 4];
            float4 bA = *(const float4*)&Bs[k][tx * 8];
            float4 bB = *(const float4*)&Bs[k][tx * 8 + 4];
            float a[8] = {aA.x, aA.y, aA.z, aA.w, aB.x, aB.y, aB.z, aB.w};
            float b[8] = {bA.x, bA.y, bA.z, bA.w, bB.x, bB.y, bB.z, bB.w};
#pragma unroll
            for (int i = 0; i < 8; i++)
#pragma unroll
                for (int j = 0; j < 8; j++) acc[i][j] += a[i] * b[j];
        }
        __syncthreads();
    }

    float bias[8];
    const float* bb = b2 + (size_t)e * KDIM + col0 + tx * 8;
#pragma unroll
    for (int j = 0; j < 8; j++) bias[j] = bb[j];

#pragma unroll
    for (int i = 0; i < 8; i++) {
        int gr = row0 + ty * 8 + i;
        if (gr < cnt) {
            int   tok = g_tok[e * NTOK + gr];
            float g   = g_gate[e * NTOK + gr];
            float* op = out + (size_t)tok * KDIM + col0 + tx * 8;
#pragma unroll
            for (int j = 0; j < 8; j++) {
                float y = acc[i][j] + bias[j];
                op[j] += g * expf(y);
            }
        }
    }
}

// ---------------------------------------------------------------------------
__global__ void finalize_kernel(float* __restrict__ out, int n) {
    int i = blockIdx.x * blockDim.x + threadIdx.x;
    if (i < n) {
        float v = out[i];
        out[i] = logf(v == 0.0f ? 2.2204460492503131e-16f : v);
    }
}

// ---------------------------------------------------------------------------
extern "C" void kernel_launch(void* const* d_in, const int* in_sizes, int n_in,
                              void* d_out, int out_size) {
    const float* x  = (const float*)d_in[0];
    const float* wg = (const float*)d_in[1];
    const float* W1 = (const float*)d_in[2];
    const float* b1 = (const float*)d_in[3];
    const float* W2 = (const float*)d_in[4];
    const float* b2 = (const float*)d_in[5];
    float* out = (float*)d_out;

    cudaMemsetAsync(out, 0, (size_t)NTOK * KDIM * sizeof(float), 0);
    zero_counts_kernel<<<1, 32>>>();
    gating_kernel<<<(NTOK * 32 + 255) / 256, 256>>>(x, wg);

    for (int e = 0; e < NEXP; e++) {
        dim3 g1(KHID / 128, NTOK / 128);   // (24, 128)
        fc1_mma_kernel<<<g1, 256>>>(x, W1, b1, e);
        dim3 g2(KDIM / BN, NTOK / BM);     // (6, 128)
        fc2_kernel<<<g2, 256>>>(W2, b2, out, e);
    }

    finalize_kernel<<<(NTOK * KDIM + 255) / 256, 256>>>(out, NTOK * KDIM);
}

// round 7
// speedup vs baseline: 1.7516x; 1.4555x over previous
#include <cuda_runtime.h>
#include <cuda_bf16.h>
#include <math.h>
#include <stdint.h>

#define NTOK 16384
#define KDIM 768
#define KHID 3072
#define NEXP 5

// ---------------- device scratch (static, allocation-free) ----------------
__device__ int   g_count[NEXP];
__device__ int   g_tok[NEXP * NTOK];
__device__ float g_gate[NEXP * NTOK];
__device__ float g_H[(size_t)NTOK * KHID];   // fp32 hidden scratch

// ---------------- helpers ----------------
__device__ __forceinline__ void mma16816(float (&c)[4], const uint32_t (&a)[4],
                                         uint32_t b0, uint32_t b1) {
    asm volatile("mma.sync.aligned.m16n8k16.row.col.f32.bf16.bf16.f32 "
                 "{%0,%1,%2,%3}, {%4,%5,%6,%7}, {%8,%9}, {%0,%1,%2,%3};"
                 : "+f"(c[0]), "+f"(c[1]), "+f"(c[2]), "+f"(c[3])
                 : "r"(a[0]), "r"(a[1]), "r"(a[2]), "r"(a[3]), "r"(b0), "r"(b1));
}
// split (fx, fy) -> packed bf16x2 hi and bf16x2 lo (residual). 6 SASS ops.
__device__ __forceinline__ void split2(float fx, float fy, uint32_t& hi, uint32_t& lo) {
    uint32_t h;
    asm("cvt.rn.bf16x2.f32 %0, %1, %2;" : "=r"(h) : "f"(fy), "f"(fx));
    float lx = fx - __uint_as_float(h << 16);
    float ly = fy - __uint_as_float(h & 0xffff0000u);
    asm("cvt.rn.bf16x2.f32 %0, %1, %2;" : "=r"(lo) : "f"(ly), "f"(lx));
    hi = h;
}
__device__ __forceinline__ float gelu_erf(float v) {
    return 0.5f * v * (1.0f + erff(v * 0.70710678118654752f));
}

// ---------------------------------------------------------------------------
__global__ void zero_counts_kernel() {
    if (threadIdx.x < NEXP) g_count[threadIdx.x] = 0;
}

__global__ void gating_kernel(const float* __restrict__ x, const float* __restrict__ wg) {
    int t = (blockIdx.x * blockDim.x + threadIdx.x) >> 5;
    int lane = threadIdx.x & 31;
    if (t >= NTOK) return;
    const float* xr = x + (size_t)t * KDIM;
    float p0 = 0.f, p1 = 0.f, p2 = 0.f, p3 = 0.f, p4 = 0.f;
    for (int k = lane; k < KDIM; k += 32) {
        float xv = xr[k];
        const float* w = wg + (size_t)k * NEXP;
        p0 += xv * w[0]; p1 += xv * w[1]; p2 += xv * w[2]; p3 += xv * w[3]; p4 += xv * w[4];
    }
#pragma unroll
    for (int o = 16; o > 0; o >>= 1) {
        p0 += __shfl_down_sync(0xffffffffu, p0, o);
        p1 += __shfl_down_sync(0xffffffffu, p1, o);
        p2 += __shfl_down_sync(0xffffffffu, p2, o);
        p3 += __shfl_down_sync(0xffffffffu, p3, o);
        p4 += __shfl_down_sync(0xffffffffu, p4, o);
    }
    if (lane == 0) {
        float v[NEXP] = {p0, p1, p2, p3, p4};
        int i0 = 0; float v0 = v[0];
#pragma unroll
        for (int e = 1; e < NEXP; e++) if (v[e] > v0) { v0 = v[e]; i0 = e; }
        int i1 = -1; float v1 = -3.4e38f;
#pragma unroll
        for (int e = 0; e < NEXP; e++) if (e != i0 && v[e] > v1) { v1 = v[e]; i1 = e; }
        float e1 = expf(v1 - v0);
        float s = 1.0f + e1;
        int q0 = atomicAdd(&g_count[i0], 1);
        g_tok[i0 * NTOK + q0] = t;  g_gate[i0 * NTOK + q0] = 1.0f / s;
        int q1 = atomicAdd(&g_count[i1], 1);
        g_tok[i1 * NTOK + q1] = t;  g_gate[i1 * NTOK + q1] = e1 / s;
    }
}

// ---------------------------------------------------------------------------
// Shared GEMM skeleton (proven in R6): 128x128 CTA tile, 8 warps (4x2), warp
// tile 32x64, fp32 LDG->STS double buffer, in-register bf16 hi/lo split,
// 3-term mma (ahbh + albh + ahbl).
#define CKE 16
#define A_STR 20     // floats per SMEM A row (16 + pad)
#define B_STR 136    // floats per SMEM B row (128 + pad)

// MODE 0 (fc1): A = gathered x rows [*,768], B = W1[e] [768,3072];
//               epi: g_H = gelu(acc + b1)
// MODE 1 (fc2): A = g_H [*,3072],          B = W2[e] [3072,768];
//               epi: out[tok] += gate * exp(acc + b2)
template <int MODE>
__global__ __launch_bounds__(256, 1)
void moe_mma_kernel(const float* __restrict__ x, const float* __restrict__ W,
                    const float* __restrict__ bias, int e, float* __restrict__ out) {
    int cnt = g_count[e];
    int row0 = blockIdx.y * 128;
    if (row0 >= cnt) return;
    int col0 = blockIdx.x * 128;

    const int KE = (MODE == 0) ? KDIM : KHID;   // reduction length
    const int NB = (MODE == 0) ? KHID : KDIM;   // output width (B row stride)

    __shared__ float sA[2][128 * A_STR];
    __shared__ float sB[2][CKE * B_STR];
    __shared__ float s_bias[128];

    int tid = threadIdx.x, wid = tid >> 5, lane = tid & 31;
    int wm = (wid & 3) * 32, wn = (wid >> 2) * 64;
    int g = lane >> 2, t4 = lane & 3;

    if (tid < 128) s_bias[tid] = bias[(size_t)e * NB + col0 + tid];

    // A loader: thread -> (row lr, 8-float half lh)
    int lr = tid >> 1, lh = tid & 1;
    int arow = row0 + lr;
    const float* aSrc;
    if (MODE == 0) {
        int tokA = g_tok[e * NTOK + (arow < cnt ? arow : row0)];
        aSrc = x + (size_t)tokA * KDIM + lh * 8;
    } else {
        aSrc = g_H + (size_t)arow * KHID + lh * 8;   // garbage rows >= cnt: finite, discarded
    }
    // B loader: thread -> (k-row kr, 8-float segment seg)
    int kr = tid >> 4, seg = tid & 15;
    const float* bSrc = W + (size_t)e * KDIM * KHID + (size_t)kr * NB + col0 + seg * 8;

    float4 ra0, ra1, rb0, rb1;
    auto ldg = [&](int c) {
        const float* ap = aSrc + c * CKE;
        ra0 = *(const float4*)ap;       ra1 = *(const float4*)(ap + 4);
        const float* bp = bSrc + (size_t)c * CKE * NB;
        rb0 = *(const float4*)bp;       rb1 = *(const float4*)(bp + 4);
    };
    auto sts = [&](int s) {
        float* pa = &sA[s][lr * A_STR + lh * 8];
        *(float4*)pa = ra0;  *(float4*)(pa + 4) = ra1;
        float* pb = &sB[s][kr * B_STR + seg * 8];
        *(float4*)pb = rb0;  *(float4*)(pb + 4) = rb1;
    };

    float acc[2][8][4];
#pragma unroll
    for (int i = 0; i < 2; i++)
#pragma unroll
        for (int j = 0; j < 8; j++)
#pragma unroll
            for (int k = 0; k < 4; k++) acc[i][j][k] = 0.f;

    const int NC = KE / CKE;
    ldg(0);
    sts(0);

    for (int c = 0; c < NC; c++) {
        __syncthreads();
        if (c + 1 < NC) ldg(c + 1);

        const float* A = sA[c & 1];
        const float* B = sB[c & 1];

        uint32_t ah[2][4], al[2][4];
#pragma unroll
        for (int mt = 0; mt < 2; mt++) {
            int r0 = wm + mt * 16 + g;
            float2 f0 = *(const float2*)&A[r0 * A_STR + 2 * t4];
            float2 f1 = *(const float2*)&A[(r0 + 8) * A_STR + 2 * t4];
            float2 f2 = *(const float2*)&A[r0 * A_STR + 2 * t4 + 8];
            float2 f3 = *(const float2*)&A[(r0 + 8) * A_STR + 2 * t4 + 8];
            split2(f0.x, f0.y, ah[mt][0], al[mt][0]);
            split2(f1.x, f1.y, ah[mt][1], al[mt][1]);
            split2(f2.x, f2.y, ah[mt][2], al[mt][2]);
            split2(f3.x, f3.y, ah[mt][3], al[mt][3]);
        }
#pragma unroll
        for (int np = 0; np < 4; np++) {
            int n0 = wn + np * 16 + g;
            uint32_t bh[4], bl[4];
            split2(B[(2 * t4) * B_STR + n0],         B[(2 * t4 + 1) * B_STR + n0],     bh[0], bl[0]);
            split2(B[(2 * t4 + 8) * B_STR + n0],     B[(2 * t4 + 9) * B_STR + n0],     bh[1], bl[1]);
            split2(B[(2 * t4) * B_STR + n0 + 8],     B[(2 * t4 + 1) * B_STR + n0 + 8], bh[2], bl[2]);
            split2(B[(2 * t4 + 8) * B_STR + n0 + 8], B[(2 * t4 + 9) * B_STR + n0 + 8], bh[3], bl[3]);
#pragma unroll
            for (int mt = 0; mt < 2; mt++) {
                mma16816(acc[mt][np * 2 + 0], ah[mt], bh[0], bh[1]);
                mma16816(acc[mt][np * 2 + 0], al[mt], bh[0], bh[1]);
                mma16816(acc[mt][np * 2 + 0], ah[mt], bl[0], bl[1]);
                mma16816(acc[mt][np * 2 + 1], ah[mt], bh[2], bh[3]);
                mma16816(acc[mt][np * 2 + 1], al[mt], bh[2], bh[3]);
                mma16816(acc[mt][np * 2 + 1], ah[mt], bl[2], bl[3]);
            }
        }
        if (c + 1 < NC) sts((c + 1) & 1);
    }

    // ---- epilogue: fragment (mt): rows g / g+8; cols wn + nj*8 + 2*t4 + {0,1}
#pragma unroll
    for (int mt = 0; mt < 2; mt++) {
        int gr0 = row0 + wm + mt * 16 + g;
        int gr1 = gr0 + 8;
        bool a0 = gr0 < cnt, a1 = gr1 < cnt;
        int tok0 = 0, tok1 = 0; float gt0 = 0.f, gt1 = 0.f;
        if (MODE == 1) {
            if (a0) { tok0 = g_tok[e * NTOK + gr0]; gt0 = g_gate[e * NTOK + gr0]; }
            if (a1) { tok1 = g_tok[e * NTOK + gr1]; gt1 = g_gate[e * NTOK + gr1]; }
        }
#pragma unroll
        for (int nj = 0; nj < 8; nj++) {
            int cloc = wn + nj * 8 + 2 * t4;
            float b0v = s_bias[cloc], b1v = s_bias[cloc + 1];
            if (MODE == 0) {
                size_t o0 = (size_t)gr0 * KHID + col0 + cloc;
                size_t o1 = (size_t)gr1 * KHID + col0 + cloc;
                if (a0) {
                    g_H[o0]     = gelu_erf(acc[mt][nj][0] + b0v);
                    g_H[o0 + 1] = gelu_erf(acc[mt][nj][1] + b1v);
                }
                if (a1) {
                    g_H[o1]     = gelu_erf(acc[mt][nj][2] + b0v);
                    g_H[o1 + 1] = gelu_erf(acc[mt][nj][3] + b1v);
                }
            } else {
                int cb = col0 + cloc;
                if (a0) {
                    float* op = out + (size_t)tok0 * KDIM + cb;
                    op[0] += gt0 * expf(acc[mt][nj][0] + b0v);
                    op[1] += gt0 * expf(acc[mt][nj][1] + b1v);
                }
                if (a1) {
                    float* op = out + (size_t)tok1 * KDIM + cb;
                    op[0] += gt1 * expf(acc[mt][nj][2] + b0v);
                    op[1] += gt1 * expf(acc[mt][nj][3] + b1v);
                }
            }
        }
    }
}

// ---------------------------------------------------------------------------
__global__ void finalize_kernel(float* __restrict__ out, int n) {
    int i = blockIdx.x * blockDim.x + threadIdx.x;
    if (i < n) {
        float v = out[i];
        out[i] = logf(v == 0.0f ? 2.2204460492503131e-16f : v);
    }
}

// ---------------------------------------------------------------------------
extern "C" void kernel_launch(void* const* d_in, const int* in_sizes, int n_in,
                              void* d_out, int out_size) {
    const float* x  = (const float*)d_in[0];
    const float* wg = (const float*)d_in[1];
    const float* W1 = (const float*)d_in[2];
    const float* b1 = (const float*)d_in[3];
    const float* W2 = (const float*)d_in[4];
    const float* b2 = (const float*)d_in[5];
    float* out = (float*)d_out;

    cudaMemsetAsync(out, 0, (size_t)NTOK * KDIM * sizeof(float), 0);
    zero_counts_kernel<<<1, 32>>>();
    gating_kernel<<<(NTOK * 32 + 255) / 256, 256>>>(x, wg);

    for (int e = 0; e < NEXP; e++) {
        dim3 g1(KHID / 128, NTOK / 128);   // (24, 128)
        moe_mma_kernel<0><<<g1, 256>>>(x, W1, b1, e, out);
        dim3 g2(KDIM / 128, NTOK / 128);   // (6, 128)
        moe_mma_kernel<1><<<g2, 256>>>(g_H, W2, b2, e, out);
    }

    finalize_kernel<<<(NTOK * KDIM + 255) / 256, 256>>>(out, NTOK * KDIM);
}